// round 1
// baseline (speedup 1.0000x reference)
#include <cuda_runtime.h>

#define NB 512      // batch
#define NT 1024     // time steps
#define HID 64      // hidden
#define NG 192      // 3 * HID gates

// Scratch (static __device__ arrays; allocation-free per harness rules)
__device__ float g_xg[(size_t)NT * NB * NG];   // [t][b][g] input-side gate preacts
__device__ float g_h0[(size_t)NT * NB * HID];  // [t][b][j] layer outputs (ping)
__device__ float g_h1[(size_t)NT * NB * HID];  // (pong)

__device__ __forceinline__ float sigf(float x) {
    return __fdividef(1.f, 1.f + __expf(-x));
}
__device__ __forceinline__ float tanh_(float x) {
    // tanh(x) = 2*sigmoid(2x) - 1  (MUFU-based, ~1e-7 rel err)
    return fmaf(2.f, sigf(2.f * x), -1.f);
}

// ---------------------------------------------------------------------------
// Layer-0 input GEMM: xg[t][b][g] = b0[g] + sum_{i<5} x[b][t][i] * w0[g][i]
// ---------------------------------------------------------------------------
__global__ void k_inp0(const float* __restrict__ x,
                       const float* __restrict__ w0,
                       const float* __restrict__ b0) {
    const int g = threadIdx.x;                 // 0..191
    const int row0 = blockIdx.x * 32;          // row = t*NB + b
    __shared__ float xs[32][5];

    float w[5];
#pragma unroll
    for (int i = 0; i < 5; i++) w[i] = w0[g * 5 + i];
    const float bias = b0[g];

    for (int i = g; i < 32 * 5; i += NG) {
        int r = i / 5, c = i % 5;
        int row = row0 + r;
        int t = row / NB, b = row % NB;        // xg rows are t-major
        xs[r][c] = x[((size_t)b * NT + t) * 5 + c];
    }
    __syncthreads();

#pragma unroll 4
    for (int r = 0; r < 32; r++) {
        float acc = bias;
#pragma unroll
        for (int c = 0; c < 5; c++) acc += w[c] * xs[r][c];
        g_xg[((size_t)(row0 + r)) * NG + g] = acc;
    }
}

// ---------------------------------------------------------------------------
// Layers 1..4 input GEMM: xg[row][g] = b[g] + sum_k hin[row][k] * w_ih[g][k]
// rows = flattened (t*NB + b). 192 threads, 32 rows/block, reg-resident w row.
// ---------------------------------------------------------------------------
__global__ void k_inp(const float* __restrict__ hin,
                      const float* __restrict__ w_ih,
                      const float* __restrict__ b_ih) {
    const int g = threadIdx.x;
    const size_t row0 = (size_t)blockIdx.x * 32;
    __shared__ float hs[32][HID];

    float w[HID];
#pragma unroll
    for (int k = 0; k < HID; k += 4) {
        float4 v = *(const float4*)(w_ih + (size_t)g * HID + k);
        w[k] = v.x; w[k + 1] = v.y; w[k + 2] = v.z; w[k + 3] = v.w;
    }
    const float bias = b_ih[g];

    for (int i = g; i < 32 * HID; i += NG)
        hs[i >> 6][i & 63] = hin[row0 * HID + i];
    __syncthreads();

#pragma unroll 1
    for (int r4 = 0; r4 < 32; r4 += 4) {
        float a0 = bias, a1 = bias, a2 = bias, a3 = bias;
#pragma unroll
        for (int k = 0; k < HID; k += 4) {
            float4 h0 = *(const float4*)&hs[r4 + 0][k];
            float4 h1 = *(const float4*)&hs[r4 + 1][k];
            float4 h2 = *(const float4*)&hs[r4 + 2][k];
            float4 h3 = *(const float4*)&hs[r4 + 3][k];
            a0 += w[k] * h0.x + w[k + 1] * h0.y + w[k + 2] * h0.z + w[k + 3] * h0.w;
            a1 += w[k] * h1.x + w[k + 1] * h1.y + w[k + 2] * h1.z + w[k + 3] * h1.w;
            a2 += w[k] * h2.x + w[k + 1] * h2.y + w[k + 2] * h2.z + w[k + 3] * h2.w;
            a3 += w[k] * h3.x + w[k + 1] * h3.y + w[k + 2] * h3.z + w[k + 3] * h3.w;
        }
        g_xg[(row0 + r4 + 0) * NG + g] = a0;
        g_xg[(row0 + r4 + 1) * NG + g] = a1;
        g_xg[(row0 + r4 + 2) * NG + g] = a2;
        g_xg[(row0 + r4 + 3) * NG + g] = a3;
    }
}

// ---------------------------------------------------------------------------
// Persistent recurrent scan: 128 blocks x 192 threads; block owns 4 batch rows.
// Thread g owns gate g: w_hh row in registers. h in shared. Seq loop over T.
// Gate order (torch): r=[0:64), z=[64:128), n=[128:192).
// ---------------------------------------------------------------------------
__global__ void k_scan(const float* __restrict__ w_hh,
                       const float* __restrict__ b_hh,
                       float* __restrict__ hout) {
    const int g = threadIdx.x;
    const int b0 = blockIdx.x * 4;
    __shared__ float h_sh[4][HID];
    __shared__ float rz_sh[2][4][HID];

    float w[HID];
#pragma unroll
    for (int k = 0; k < HID; k += 4) {
        float4 v = *(const float4*)(w_hh + (size_t)g * HID + k);
        w[k] = v.x; w[k + 1] = v.y; w[k + 2] = v.z; w[k + 3] = v.w;
    }
    const float bias = b_hh[g];

    for (int i = g; i < 4 * HID; i += NG) ((float*)h_sh)[i] = 0.f;
    __syncthreads();

    // prefetch xg for t=0
    const float* p0 = g_xg + (size_t)b0 * NG + g;
    float xc0 = p0[0], xc1 = p0[NG], xc2 = p0[2 * NG], xc3 = p0[3 * NG];

    for (int t = 0; t < NT; t++) {
        // prefetch t+1 (covers global latency under the dot-product compute)
        float xn0 = 0.f, xn1 = 0.f, xn2 = 0.f, xn3 = 0.f;
        if (t + 1 < NT) {
            const float* p = g_xg + ((size_t)(t + 1) * NB + b0) * NG + g;
            xn0 = p[0]; xn1 = p[NG]; xn2 = p[2 * NG]; xn3 = p[3 * NG];
        }

        float a0 = bias, a1 = bias, a2 = bias, a3 = bias;
#pragma unroll
        for (int k = 0; k < HID; k += 4) {
            float4 h0 = *(const float4*)&h_sh[0][k];
            float4 h1 = *(const float4*)&h_sh[1][k];
            float4 h2 = *(const float4*)&h_sh[2][k];
            float4 h3 = *(const float4*)&h_sh[3][k];
            a0 += w[k] * h0.x + w[k + 1] * h0.y + w[k + 2] * h0.z + w[k + 3] * h0.w;
            a1 += w[k] * h1.x + w[k + 1] * h1.y + w[k + 2] * h1.z + w[k + 3] * h1.w;
            a2 += w[k] * h2.x + w[k + 1] * h2.y + w[k + 2] * h2.z + w[k + 3] * h2.w;
            a3 += w[k] * h3.x + w[k + 1] * h3.y + w[k + 2] * h3.z + w[k + 3] * h3.w;
        }

        if (g < 128) {
            const int which = g >> 6;   // 0 = r gate, 1 = z gate
            const int j = g & 63;
            rz_sh[which][0][j] = sigf(xc0 + a0);
            rz_sh[which][1][j] = sigf(xc1 + a1);
            rz_sh[which][2][j] = sigf(xc2 + a2);
            rz_sh[which][3][j] = sigf(xc3 + a3);
        }
        __syncthreads();
        if (g >= 128) {
            const int j = g - 128;
            float* op = hout + ((size_t)t * NB + b0) * HID + j;
            {
                float n = tanh_(xc0 + rz_sh[0][0][j] * a0);
                float z = rz_sh[1][0][j];
                float hn = n + z * (h_sh[0][j] - n);
                h_sh[0][j] = hn; op[0] = hn;
            }
            {
                float n = tanh_(xc1 + rz_sh[0][1][j] * a1);
                float z = rz_sh[1][1][j];
                float hn = n + z * (h_sh[1][j] - n);
                h_sh[1][j] = hn; op[HID] = hn;
            }
            {
                float n = tanh_(xc2 + rz_sh[0][2][j] * a2);
                float z = rz_sh[1][2][j];
                float hn = n + z * (h_sh[2][j] - n);
                h_sh[2][j] = hn; op[2 * HID] = hn;
            }
            {
                float n = tanh_(xc3 + rz_sh[0][3][j] * a3);
                float z = rz_sh[1][3][j];
                float hn = n + z * (h_sh[3][j] - n);
                h_sh[3][j] = hn; op[3 * HID] = hn;
            }
        }
        __syncthreads();
        xc0 = xn0; xc1 = xn1; xc2 = xn2; xc3 = xn3;
    }
}

// ---------------------------------------------------------------------------
// Final FC on last timestep: out[b] = h[T-1][b][:] . w_fc + b_fc
// ---------------------------------------------------------------------------
__global__ void k_fc(const float* __restrict__ hin,
                     const float* __restrict__ w_fc,
                     const float* __restrict__ b_fc,
                     float* __restrict__ out) {
    int b = blockIdx.x * blockDim.x + threadIdx.x;
    if (b >= NB) return;
    const float* hp = hin + ((size_t)(NT - 1) * NB + b) * HID;
    float acc = b_fc[0];
#pragma unroll
    for (int k = 0; k < HID; k++) acc += hp[k] * w_fc[k];
    out[b] = acc;
}

// ---------------------------------------------------------------------------
extern "C" void kernel_launch(void* const* d_in, const int* in_sizes, int n_in,
                              void* d_out, int out_size) {
    const float* x     = (const float*)d_in[0];
    const float* w_ih0 = (const float*)d_in[1];
    const float* w_hh0 = (const float*)d_in[2];
    const float* b_ih0 = (const float*)d_in[3];
    const float* b_hh0 = (const float*)d_in[4];
    const float* w_ih  = (const float*)d_in[5];   // [4][192][64]
    const float* w_hh  = (const float*)d_in[6];   // [4][192][64]
    const float* b_ih  = (const float*)d_in[7];   // [4][192]
    const float* b_hh  = (const float*)d_in[8];   // [4][192]
    const float* w_fc  = (const float*)d_in[9];
    const float* b_fc  = (const float*)d_in[10];
    float* out = (float*)d_out;

    float *hA = nullptr, *hB = nullptr;
    cudaGetSymbolAddress((void**)&hA, g_h0);
    cudaGetSymbolAddress((void**)&hB, g_h1);

    const int gemm_blocks = (NT * NB) / 32;  // 16384

    // Layer 0
    k_inp0<<<gemm_blocks, NG>>>(x, w_ih0, b_ih0);
    k_scan<<<NB / 4, NG>>>(w_hh0, b_hh0, hA);

    // Layers 1..4
    float* hin = hA;
    float* hou = hB;
    for (int L = 0; L < 4; L++) {
        k_inp<<<gemm_blocks, NG>>>(hin, w_ih + (size_t)L * NG * HID, b_ih + L * NG);
        k_scan<<<NB / 4, NG>>>(w_hh + (size_t)L * NG * HID, b_hh + L * NG, hou);
        float* tmp = hin; hin = hou; hou = tmp;
    }

    // FC head on last timestep (hin holds the last layer's output)
    k_fc<<<2, 256>>>(hin, w_fc, b_fc, out);
}

// round 2
// speedup vs baseline: 2.6030x; 2.6030x over previous
#include <cuda_runtime.h>

#define NB 512      // batch
#define NT 1024     // time steps
#define HID 64      // hidden
#define NG 192      // 3 * HID gates

// Scratch (static __device__ arrays; allocation-free per harness rules)
__device__ float g_xg[(size_t)NT * NB * NG];   // [t][b][g] input-side gate preacts
__device__ float g_h0[(size_t)NT * NB * HID];  // [t][b][j] layer outputs (ping)
__device__ float g_h1[(size_t)NT * NB * HID];  // (pong)

__device__ __forceinline__ float sigf(float x) {
    return __fdividef(1.f, 1.f + __expf(-x));
}
__device__ __forceinline__ float tanh_(float x) {
    return fmaf(2.f, sigf(2.f * x), -1.f);
}

// packed fp32x2 FMA: d = a*b + c (per 32-bit lane)
__device__ __forceinline__ unsigned long long ffma2(unsigned long long a,
                                                    unsigned long long b,
                                                    unsigned long long c) {
    unsigned long long d;
    asm("fma.rn.f32x2 %0, %1, %2, %3;" : "=l"(d) : "l"(a), "l"(b), "l"(c));
    return d;
}
__device__ __forceinline__ float f2sum(unsigned long long v) {
    return __uint_as_float((unsigned)v) + __uint_as_float((unsigned)(v >> 32));
}

// ---------------------------------------------------------------------------
// Layer-0 input GEMM: xg[t][b][g] = b0[g] + sum_{i<5} x[b][t][i] * w0[g][i]
// ---------------------------------------------------------------------------
__global__ void k_inp0(const float* __restrict__ x,
                       const float* __restrict__ w0,
                       const float* __restrict__ b0) {
    const int g = threadIdx.x;                 // 0..191
    const int row0 = blockIdx.x * 32;          // row = t*NB + b
    __shared__ float xs[32][5];

    float w[5];
#pragma unroll
    for (int i = 0; i < 5; i++) w[i] = w0[g * 5 + i];
    const float bias = b0[g];

    for (int i = g; i < 32 * 5; i += NG) {
        int r = i / 5, c = i % 5;
        int row = row0 + r;
        int t = row / NB, b = row % NB;        // xg rows are t-major
        xs[r][c] = x[((size_t)b * NT + t) * 5 + c];
    }
    __syncthreads();

#pragma unroll 4
    for (int r = 0; r < 32; r++) {
        float acc = bias;
#pragma unroll
        for (int c = 0; c < 5; c++) acc += w[c] * xs[r][c];
        g_xg[((size_t)(row0 + r)) * NG + g] = acc;
    }
}

// ---------------------------------------------------------------------------
// Layers 1..4 input GEMM (f32x2): xg[row][g] = b[g] + hin[row][:] . w_ih[g][:]
// 192 threads, 32 rows/block, weight row packed in 32 x f32x2 registers.
// ---------------------------------------------------------------------------
__global__ void k_inp(const float* __restrict__ hin,
                      const float* __restrict__ w_ih,
                      const float* __restrict__ b_ih) {
    const int g = threadIdx.x;
    const size_t row0 = (size_t)blockIdx.x * 32;
    __shared__ __align__(16) float hs[32][HID];

    unsigned long long w2[32];
    const ulonglong2* wp = (const ulonglong2*)(w_ih + (size_t)g * HID);
#pragma unroll
    for (int k = 0; k < 16; k++) {
        ulonglong2 v = wp[k];
        w2[2 * k] = v.x; w2[2 * k + 1] = v.y;
    }
    const float bias = b_ih[g];

    // 32 rows x 64 floats = 512 float4
    const float4* src = (const float4*)(hin + row0 * HID);
    float4* dst = (float4*)hs;
    for (int i = g; i < 512; i += NG) dst[i] = src[i];
    __syncthreads();

#pragma unroll 1
    for (int r2 = 0; r2 < 32; r2 += 2) {
        unsigned long long a00 = 0, a01 = 0, a10 = 0, a11 = 0;
        const ulonglong2* h0 = (const ulonglong2*)hs[r2];
        const ulonglong2* h1 = (const ulonglong2*)hs[r2 + 1];
#pragma unroll
        for (int k = 0; k < 16; k++) {
            ulonglong2 v0 = h0[k];
            ulonglong2 v1 = h1[k];
            a00 = ffma2(w2[2 * k],     v0.x, a00);
            a01 = ffma2(w2[2 * k + 1], v0.y, a01);
            a10 = ffma2(w2[2 * k],     v1.x, a10);
            a11 = ffma2(w2[2 * k + 1], v1.y, a11);
        }
        g_xg[(row0 + r2) * NG + g]     = bias + f2sum(a00) + f2sum(a01);
        g_xg[(row0 + r2 + 1) * NG + g] = bias + f2sum(a10) + f2sum(a11);
    }
}

// ---------------------------------------------------------------------------
// Persistent recurrent scan (f32x2): 256 blocks x 192 threads, 2 batch rows
// per block (2 blocks/SM -> 12 warps/SM). Thread g owns gate g, w_hh row in
// packed f32x2 registers, h in shared (broadcast LDS.128 reads).
// Gate order (torch): r=[0:64), z=[64:128), n=[128:192).
// ---------------------------------------------------------------------------
__global__ __launch_bounds__(192, 2)
void k_scan(const float* __restrict__ w_hh,
            const float* __restrict__ b_hh,
            float* __restrict__ hout, int store_all) {
    const int g = threadIdx.x;
    const int b0 = blockIdx.x * 2;
    __shared__ __align__(16) float h_sh[2][HID];
    __shared__ float rz_sh[2][2][HID];   // [r|z][row][j]

    unsigned long long w2[32];
    const ulonglong2* wp = (const ulonglong2*)(w_hh + (size_t)g * HID);
#pragma unroll
    for (int k = 0; k < 16; k++) {
        ulonglong2 v = wp[k];
        w2[2 * k] = v.x; w2[2 * k + 1] = v.y;
    }
    const float bias = b_hh[g];

    if (g < 2 * HID) ((float*)h_sh)[g] = 0.f;
    __syncthreads();

    const float* xb = g_xg + (size_t)b0 * NG + g;
    float xc0 = xb[0], xc1 = xb[NG];

    for (int t = 0; t < NT; t++) {
        // prefetch next step's xg (hidden under the dot products)
        float xn0 = 0.f, xn1 = 0.f;
        if (t + 1 < NT) {
            const float* p = xb + (size_t)(t + 1) * NB * NG;
            xn0 = p[0]; xn1 = p[NG];
        }

        unsigned long long a00 = 0, a01 = 0, a10 = 0, a11 = 0;
        const ulonglong2* h0 = (const ulonglong2*)h_sh[0];
        const ulonglong2* h1 = (const ulonglong2*)h_sh[1];
#pragma unroll
        for (int k = 0; k < 16; k++) {
            ulonglong2 v0 = h0[k];
            ulonglong2 v1 = h1[k];
            a00 = ffma2(w2[2 * k],     v0.x, a00);
            a01 = ffma2(w2[2 * k + 1], v0.y, a01);
            a10 = ffma2(w2[2 * k],     v1.x, a10);
            a11 = ffma2(w2[2 * k + 1], v1.y, a11);
        }
        float s0 = bias + f2sum(a00) + f2sum(a01);
        float s1 = bias + f2sum(a10) + f2sum(a11);

        if (g < 128) {                       // r and z gates
            const int which = g >> 6;        // 0 = r, 1 = z
            const int j = g & 63;
            rz_sh[which][0][j] = sigf(xc0 + s0);
            rz_sh[which][1][j] = sigf(xc1 + s1);
        }
        __syncthreads();                     // rz ready; all dot-reads of h_sh done
        if (g >= 128) {                      // n gate + state update
            const int j = g - 128;
            float n0 = tanh_(xc0 + rz_sh[0][0][j] * s0);
            float z0 = rz_sh[1][0][j];
            float hp0 = h_sh[0][j];
            float hn0 = n0 + z0 * (hp0 - n0);
            h_sh[0][j] = hn0;

            float n1 = tanh_(xc1 + rz_sh[0][1][j] * s1);
            float z1 = rz_sh[1][1][j];
            float hp1 = h_sh[1][j];
            float hn1 = n1 + z1 * (hp1 - n1);
            h_sh[1][j] = hn1;

            if (store_all || t == NT - 1) {
                float* op = hout + ((size_t)t * NB + b0) * HID + j;
                op[0] = hn0;
                op[HID] = hn1;
            }
        }
        __syncthreads();                     // h_sh updated for next step
        xc0 = xn0; xc1 = xn1;
    }
}

// ---------------------------------------------------------------------------
// Final FC on last timestep: out[b] = h[T-1][b][:] . w_fc + b_fc
// ---------------------------------------------------------------------------
__global__ void k_fc(const float* __restrict__ hin,
                     const float* __restrict__ w_fc,
                     const float* __restrict__ b_fc,
                     float* __restrict__ out) {
    int b = blockIdx.x * blockDim.x + threadIdx.x;
    if (b >= NB) return;
    const float* hp = hin + ((size_t)(NT - 1) * NB + b) * HID;
    float acc = b_fc[0];
#pragma unroll
    for (int k = 0; k < HID; k++) acc += hp[k] * w_fc[k];
    out[b] = acc;
}

// ---------------------------------------------------------------------------
extern "C" void kernel_launch(void* const* d_in, const int* in_sizes, int n_in,
                              void* d_out, int out_size) {
    const float* x     = (const float*)d_in[0];
    const float* w_ih0 = (const float*)d_in[1];
    const float* w_hh0 = (const float*)d_in[2];
    const float* b_ih0 = (const float*)d_in[3];
    const float* b_hh0 = (const float*)d_in[4];
    const float* w_ih  = (const float*)d_in[5];   // [4][192][64]
    const float* w_hh  = (const float*)d_in[6];   // [4][192][64]
    const float* b_ih  = (const float*)d_in[7];   // [4][192]
    const float* b_hh  = (const float*)d_in[8];   // [4][192]
    const float* w_fc  = (const float*)d_in[9];
    const float* b_fc  = (const float*)d_in[10];
    float* out = (float*)d_out;

    float *hA = nullptr, *hB = nullptr;
    cudaGetSymbolAddress((void**)&hA, g_h0);
    cudaGetSymbolAddress((void**)&hB, g_h1);

    const int gemm_blocks = (NT * NB) / 32;  // 16384

    // Layer 0
    k_inp0<<<gemm_blocks, NG>>>(x, w_ih0, b_ih0);
    k_scan<<<NB / 2, NG>>>(w_hh0, b_hh0, hA, 1);

    // Layers 1..4
    float* hin = hA;
    float* hou = hB;
    for (int L = 0; L < 4; L++) {
        int last = (L == 3);
        k_inp<<<gemm_blocks, NG>>>(hin, w_ih + (size_t)L * NG * HID, b_ih + L * NG);
        k_scan<<<NB / 2, NG>>>(w_hh + (size_t)L * NG * HID, b_hh + L * NG, hou, !last);
        float* tmp = hin; hin = hou; hou = tmp;
    }

    // FC head on last timestep (hin holds the last layer's output)
    k_fc<<<2, 256>>>(hin, w_fc, b_fc, out);
}